// round 9
// baseline (speedup 1.0000x reference)
#include <cuda_runtime.h>

// InnerProduct: ip[r,p] = sum_f w[p,f]^2 * sum_e x[r,f,e]^2
// x: [32768, 64, 128] f32, w: [10, 64] f32, out: [32768, 10] f32
//
// FINAL (converged): DRAM-bound 1 GiB single-pass read of x, running at
// 91.9% of HBM spec (7.28 TB/s; ideal floor 134us, measured 148.2us).
// One-shot CTA per row, 8 warps x 8 fields, 8 front-batched streaming
// LDG.128/thread (__ldcs: x is single-use, evict-first), 9-SHFL fold-and-
// split multi-value warp reduce, one __syncthreads, 160-thread tail.
// regs=32 -> 8 CTAs/SM (binding constraint, proven by R4's regression).

#define BATCH    32768
#define N_FIELDS 64
#define EMBED    128
#define OUT_SZ   10
#define THREADS  256

__global__ __launch_bounds__(THREADS)
void innerproduct_kernel(const float* __restrict__ x,
                         const float* __restrict__ w,
                         float* __restrict__ out)
{
    const int r    = blockIdx.x;
    const int tid  = threadIdx.x;
    const int warp = tid >> 5;
    const int lane = tid & 31;

    __shared__ float xsq[N_FIELDS];

    // Warp owns fields warp*8 .. warp*8+7 (contiguous 4KB of the row);
    // lane l takes float4 #l of each field. 8 independent LDG.128, streaming.
    const float4* __restrict__ xr =
        reinterpret_cast<const float4*>(x)
        + (size_t)r * (N_FIELDS * EMBED / 4) + warp * 8 * (EMBED / 4) + lane;

    float4 vv[8];
#pragma unroll
    for (int i = 0; i < 8; i++)
        vv[i] = __ldcs(&xr[i * (EMBED / 4)]);

    // Weight loads (reused by every CTA -> default caching) issue now so
    // their latency hides under the x-load wait.
    const int p = tid >> 4;   // output 0..9 for tid < 160
    const int g = tid & 15;   // owns fields g*4..g*4+3
    float wsq[4] = {0.f, 0.f, 0.f, 0.f};
    if (tid < OUT_SZ * 16) {
#pragma unroll
        for (int k = 0; k < 4; k++) {
            float wv = __ldg(&w[p * N_FIELDS + g * 4 + k]);
            wsq[k] = wv * wv;
        }
    }

    float v[8];
#pragma unroll
    for (int i = 0; i < 8; i++)
        v[i] = vv[i].x * vv[i].x + vv[i].y * vv[i].y
             + vv[i].z * vv[i].z + vv[i].w * vv[i].w;

    // Fold-and-split multi-value warp reduce: 8 -> 1 per lane in 9 SHFLs.
    // Afterward lane l holds the full sum of field warp*8 + ((l>>2)&7).
    {
        const bool hi16 = (lane & 16) != 0;
#pragma unroll
        for (int j = 0; j < 4; j++) {
            float send = hi16 ? v[j] : v[j + 4];
            float recv = __shfl_xor_sync(0xffffffffu, send, 16);
            v[j] = (hi16 ? v[j + 4] : v[j]) + recv;
        }
        const bool hi8 = (lane & 8) != 0;
#pragma unroll
        for (int j = 0; j < 2; j++) {
            float send = hi8 ? v[j] : v[j + 2];
            float recv = __shfl_xor_sync(0xffffffffu, send, 8);
            v[j] = (hi8 ? v[j + 2] : v[j]) + recv;
        }
        const bool hi4 = (lane & 4) != 0;
        {
            float send = hi4 ? v[0] : v[1];
            float recv = __shfl_xor_sync(0xffffffffu, send, 4);
            v[0] = (hi4 ? v[1] : v[0]) + recv;
        }
        v[0] += __shfl_xor_sync(0xffffffffu, v[0], 2);
        v[0] += __shfl_xor_sync(0xffffffffu, v[0], 1);
    }
    if ((lane & 3) == 0)
        xsq[warp * 8 + ((lane >> 2) & 7)] = v[0];
    __syncthreads();

    // Tail: 10 outputs x 16 threads (warps 0..4).
    if (tid < OUT_SZ * 16) {
        float s = 0.f;
#pragma unroll
        for (int k = 0; k < 4; k++)
            s = fmaf(xsq[g * 4 + k], wsq[k], s);
#pragma unroll
        for (int sh = 8; sh >= 1; sh >>= 1)
            s += __shfl_xor_sync(0xffffffffu, s, sh);
        if (g == 0)
            __stcs(&out[r * OUT_SZ + p], s);
    }
}

extern "C" void kernel_launch(void* const* d_in, const int* in_sizes, int n_in,
                              void* d_out, int out_size)
{
    const float* x = (const float*)d_in[0];
    const float* w = (const float*)d_in[1];
    float* out = (float*)d_out;

    innerproduct_kernel<<<BATCH, THREADS>>>(x, w, out);
}

// round 10
// speedup vs baseline: 1.0047x; 1.0047x over previous
#include <cuda_runtime.h>

// InnerProduct: ip[r,p] = sum_f w[p,f]^2 * sum_e x[r,f,e]^2
// x: [32768, 64, 128] f32, w: [10, 64] f32, out: [32768, 10] f32
//
// DRAM-bound 1 GiB single-pass read of x at ~92% of HBM spec (measured
// plateau, noise band +-1.5us). One-shot CTA per row, 8 warps x 8 fields,
// 8 front-batched streaming LDG.128/thread (__ldcs), 9-SHFL fold-and-split
// warp reduce, one __syncthreads, 160-thread tail. This variant vectorizes
// the tail's weight fetch into a single LDG.128 per tail thread (w rows are
// 16B-aligned), cutting per-CTA weight LDG issue count 160 -> 40 so fewer
// LSU slots are stolen from the x-load stream. regs<=32 -> 8 CTAs/SM.

#define BATCH    32768
#define N_FIELDS 64
#define EMBED    128
#define OUT_SZ   10
#define THREADS  256

__global__ __launch_bounds__(THREADS)
void innerproduct_kernel(const float* __restrict__ x,
                         const float* __restrict__ w,
                         float* __restrict__ out)
{
    const int r    = blockIdx.x;
    const int tid  = threadIdx.x;
    const int warp = tid >> 5;
    const int lane = tid & 31;

    __shared__ float xsq[N_FIELDS];

    // Warp owns fields warp*8 .. warp*8+7 (contiguous 4KB of the row);
    // lane l takes float4 #l of each field. 8 independent LDG.128, streaming.
    const float4* __restrict__ xr =
        reinterpret_cast<const float4*>(x)
        + (size_t)r * (N_FIELDS * EMBED / 4) + warp * 8 * (EMBED / 4) + lane;

    float4 vv[8];
#pragma unroll
    for (int i = 0; i < 8; i++)
        vv[i] = __ldcs(&xr[i * (EMBED / 4)]);

    // Tail weight fetch: one LDG.128 per tail thread (w[p][g*4..g*4+3]).
    // Issued now so its latency hides under the x-load wait; L1-hot after
    // the first CTAs on each SM.
    const int p = tid >> 4;   // output 0..9 for tid < 160
    const int g = tid & 15;   // owns fields g*4..g*4+3
    float wsq[4] = {0.f, 0.f, 0.f, 0.f};
    if (tid < OUT_SZ * 16) {
        float4 wv = __ldg(reinterpret_cast<const float4*>(w) +
                          (p * N_FIELDS + g * 4) / 4);
        wsq[0] = wv.x * wv.x;
        wsq[1] = wv.y * wv.y;
        wsq[2] = wv.z * wv.z;
        wsq[3] = wv.w * wv.w;
    }

    float v[8];
#pragma unroll
    for (int i = 0; i < 8; i++)
        v[i] = vv[i].x * vv[i].x + vv[i].y * vv[i].y
             + vv[i].z * vv[i].z + vv[i].w * vv[i].w;

    // Fold-and-split multi-value warp reduce: 8 -> 1 per lane in 9 SHFLs.
    // Afterward lane l holds the full sum of field warp*8 + ((l>>2)&7).
    {
        const bool hi16 = (lane & 16) != 0;
#pragma unroll
        for (int j = 0; j < 4; j++) {
            float send = hi16 ? v[j] : v[j + 4];
            float recv = __shfl_xor_sync(0xffffffffu, send, 16);
            v[j] = (hi16 ? v[j + 4] : v[j]) + recv;
        }
        const bool hi8 = (lane & 8) != 0;
#pragma unroll
        for (int j = 0; j < 2; j++) {
            float send = hi8 ? v[j] : v[j + 2];
            float recv = __shfl_xor_sync(0xffffffffu, send, 8);
            v[j] = (hi8 ? v[j + 2] : v[j]) + recv;
        }
        const bool hi4 = (lane & 4) != 0;
        {
            float send = hi4 ? v[0] : v[1];
            float recv = __shfl_xor_sync(0xffffffffu, send, 4);
            v[0] = (hi4 ? v[1] : v[0]) + recv;
        }
        v[0] += __shfl_xor_sync(0xffffffffu, v[0], 2);
        v[0] += __shfl_xor_sync(0xffffffffu, v[0], 1);
    }
    if ((lane & 3) == 0)
        xsq[warp * 8 + ((lane >> 2) & 7)] = v[0];
    __syncthreads();

    // Tail: 10 outputs x 16 threads (warps 0..4).
    if (tid < OUT_SZ * 16) {
        float s = 0.f;
#pragma unroll
        for (int k = 0; k < 4; k++)
            s = fmaf(xsq[g * 4 + k], wsq[k], s);
#pragma unroll
        for (int sh = 8; sh >= 1; sh >>= 1)
            s += __shfl_xor_sync(0xffffffffu, s, sh);
        if (g == 0)
            __stcs(&out[r * OUT_SZ + p], s);
    }
}

extern "C" void kernel_launch(void* const* d_in, const int* in_sizes, int n_in,
                              void* d_out, int out_size)
{
    const float* x = (const float*)d_in[0];
    const float* w = (const float*)d_in[1];
    float* out = (float*)d_out;

    innerproduct_kernel<<<BATCH, THREADS>>>(x, w, out);
}

// round 11
// speedup vs baseline: 1.0156x; 1.0108x over previous
#include <cuda_runtime.h>

// InnerProduct: ip[r,p] = sum_f w[p,f]^2 * sum_e x[r,f,e]^2
// x: [32768, 64, 128] f32, w: [10, 64] f32, out: [32768, 10] f32
//
// FINAL (converged over 10 rounds): DRAM-bound 1 GiB single-pass read of x
// at ~91-92% of HBM spec (7.2-7.3 TB/s; ideal floor 134us, measured
// 148-150us plateau, run-to-run noise +-1.5us).
//
// Structure: one-shot CTA per row (massive oversubscription keeps the load
// pipe full -- persistence regressed to 75% DRAM), 8 warps x 8 fields,
// 8 front-batched streaming LDG.128/thread (__ldcs: x is single-use,
// evict-first), 9-SHFL fold-and-split multi-value warp reduce, one plain
// __syncthreads (split-barrier regressed), 160-thread tail with one
// vectorized LDG.128 weight fetch per tail thread and __stcs output.
// regs=31 -> 8 CTAs/SM (binding constraint: the 47-reg variant cost 4%).

#define BATCH    32768
#define N_FIELDS 64
#define EMBED    128
#define OUT_SZ   10
#define THREADS  256

__global__ __launch_bounds__(THREADS)
void innerproduct_kernel(const float* __restrict__ x,
                         const float* __restrict__ w,
                         float* __restrict__ out)
{
    const int r    = blockIdx.x;
    const int tid  = threadIdx.x;
    const int warp = tid >> 5;
    const int lane = tid & 31;

    __shared__ float xsq[N_FIELDS];

    // Warp owns fields warp*8 .. warp*8+7 (contiguous 4KB of the row);
    // lane l takes float4 #l of each field. 8 independent LDG.128, streaming.
    const float4* __restrict__ xr =
        reinterpret_cast<const float4*>(x)
        + (size_t)r * (N_FIELDS * EMBED / 4) + warp * 8 * (EMBED / 4) + lane;

    float4 vv[8];
#pragma unroll
    for (int i = 0; i < 8; i++)
        vv[i] = __ldcs(&xr[i * (EMBED / 4)]);

    // Tail weight fetch: one LDG.128 per tail thread (w[p][g*4..g*4+3],
    // 16B-aligned). Issued now so its latency hides under the x-load wait;
    // L1/L2-hot after the first CTAs on each SM.
    const int p = tid >> 4;   // output 0..9 for tid < 160
    const int g = tid & 15;   // owns fields g*4..g*4+3
    float wsq[4] = {0.f, 0.f, 0.f, 0.f};
    if (tid < OUT_SZ * 16) {
        float4 wv = __ldg(reinterpret_cast<const float4*>(w) +
                          (p * N_FIELDS + g * 4) / 4);
        wsq[0] = wv.x * wv.x;
        wsq[1] = wv.y * wv.y;
        wsq[2] = wv.z * wv.z;
        wsq[3] = wv.w * wv.w;
    }

    float v[8];
#pragma unroll
    for (int i = 0; i < 8; i++)
        v[i] = vv[i].x * vv[i].x + vv[i].y * vv[i].y
             + vv[i].z * vv[i].z + vv[i].w * vv[i].w;

    // Fold-and-split multi-value warp reduce: 8 -> 1 per lane in 9 SHFLs.
    // Afterward lane l holds the full sum of field warp*8 + ((l>>2)&7).
    {
        const bool hi16 = (lane & 16) != 0;
#pragma unroll
        for (int j = 0; j < 4; j++) {
            float send = hi16 ? v[j] : v[j + 4];
            float recv = __shfl_xor_sync(0xffffffffu, send, 16);
            v[j] = (hi16 ? v[j + 4] : v[j]) + recv;
        }
        const bool hi8 = (lane & 8) != 0;
#pragma unroll
        for (int j = 0; j < 2; j++) {
            float send = hi8 ? v[j] : v[j + 2];
            float recv = __shfl_xor_sync(0xffffffffu, send, 8);
            v[j] = (hi8 ? v[j + 2] : v[j]) + recv;
        }
        const bool hi4 = (lane & 4) != 0;
        {
            float send = hi4 ? v[0] : v[1];
            float recv = __shfl_xor_sync(0xffffffffu, send, 4);
            v[0] = (hi4 ? v[1] : v[0]) + recv;
        }
        v[0] += __shfl_xor_sync(0xffffffffu, v[0], 2);
        v[0] += __shfl_xor_sync(0xffffffffu, v[0], 1);
    }
    if ((lane & 3) == 0)
        xsq[warp * 8 + ((lane >> 2) & 7)] = v[0];
    __syncthreads();

    // Tail: 10 outputs x 16 threads (warps 0..4).
    if (tid < OUT_SZ * 16) {
        float s = 0.f;
#pragma unroll
        for (int k = 0; k < 4; k++)
            s = fmaf(xsq[g * 4 + k], wsq[k], s);
#pragma unroll
        for (int sh = 8; sh >= 1; sh >>= 1)
            s += __shfl_xor_sync(0xffffffffu, s, sh);
        if (g == 0)
            __stcs(&out[r * OUT_SZ + p], s);
    }
}

extern "C" void kernel_launch(void* const* d_in, const int* in_sizes, int n_in,
                              void* d_out, int out_size)
{
    const float* x = (const float*)d_in[0];
    const float* w = (const float*)d_in[1];
    float* out = (float*)d_out;

    innerproduct_kernel<<<BATCH, THREADS>>>(x, w, out);
}